// round 16
// baseline (speedup 1.0000x reference)
#include <cuda_runtime.h>

#define BB 256
#define TT 50
#define MM 20
#define EE 128
#define G3 384
#define NS 40            // single-row CTAs (longest rows)
#define GRID 148         // NS + (256-NS)/2

typedef unsigned long long u64;

// scratch (no cudaMalloc allowed)
__device__ __align__(16) float g_ub[BB*TT*EE];   // basket means (B,T,E)

__device__ __forceinline__ void fma2(u64 &acc, u64 a, u64 b){
    asm("fma.rn.f32x2 %0, %1, %2, %0;" : "+l"(acc) : "l"(a), "l"(b));
}
__device__ __forceinline__ u64 add2(u64 a, u64 b){
    u64 r; asm("add.rn.f32x2 %0, %1, %2;" : "=l"(r) : "l"(a), "l"(b));
    return r;
}
__device__ __forceinline__ float hsum2(u64 v){
    float lo, hi;
    asm("mov.b64 {%0,%1}, %2;" : "=f"(lo), "=f"(hi) : "l"(v));
    return lo + hi;
}
__device__ __forceinline__ float tanh_hw(float x){
    float y; asm("tanh.approx.f32 %0, %1;" : "=f"(y) : "f"(x));
    return y;
}
__device__ __forceinline__ float sigf(float x){          // 1 MUFU
    return 0.5f + 0.5f * tanh_hw(0.5f * x);
}
__device__ __forceinline__ int zero_dep(float x){
    int r;
    asm("{\n\t.reg .b32 t;\n\tmov.b32 t, %1;\n\tand.b32 %0, t, 0;\n\t}"
        : "=r"(r) : "f"(x));
    return r;
}

// dot of this thread's W row with a 128-float vector in SMEM (broadcast LDS)
__device__ __forceinline__ float dot_s(const u64* __restrict__ w,
                                       const float* __restrict__ src){
    u64 ca = 0ull, cb = 0ull;
    const ulonglong2* hp = (const ulonglong2*)src;
    #pragma unroll
    for (int k = 0; k < 32; ++k){
        ulonglong2 v = hp[k];
        fma2(ca, w[2*k  ], v.x);
        fma2(cb, w[2*k+1], v.y);
    }
    return hsum2(add2(ca, cb));
}

// ---------------------------------------------------------------------------
// K1: gather — low-register version (measured ~11us, occ 48%).
// One WARP per PAIR of rows (p, 12799-p), processed sequentially.
// ---------------------------------------------------------------------------
__device__ __forceinline__ void gather_row(int r, int lane,
                                           const int* __restrict__ ids,
                                           const int* __restrict__ bsz,
                                           const int* __restrict__ lens,
                                           const float4* __restrict__ e4){
    const int b = r / TT;
    const int t = r - b*TT;
    if (t >= __ldg(lens + b)) return;             // uniform per warp

    const int4* ip = (const int4*)(ids + r*MM);   // 20 ids = 5 int4, broadcast
    const int4 i0 = __ldg(ip+0), i1 = __ldg(ip+1), i2 = __ldg(ip+2),
               i3 = __ldg(ip+3), i4 = __ldg(ip+4);

    float4 v[20];
    v[0]=__ldg(e4+i0.x*32+lane);  v[1]=__ldg(e4+i0.y*32+lane);
    v[2]=__ldg(e4+i0.z*32+lane);  v[3]=__ldg(e4+i0.w*32+lane);
    v[4]=__ldg(e4+i1.x*32+lane);  v[5]=__ldg(e4+i1.y*32+lane);
    v[6]=__ldg(e4+i1.z*32+lane);  v[7]=__ldg(e4+i1.w*32+lane);
    v[8]=__ldg(e4+i2.x*32+lane);  v[9]=__ldg(e4+i2.y*32+lane);
    v[10]=__ldg(e4+i2.z*32+lane); v[11]=__ldg(e4+i2.w*32+lane);
    v[12]=__ldg(e4+i3.x*32+lane); v[13]=__ldg(e4+i3.y*32+lane);
    v[14]=__ldg(e4+i3.z*32+lane); v[15]=__ldg(e4+i3.w*32+lane);
    v[16]=__ldg(e4+i4.x*32+lane); v[17]=__ldg(e4+i4.y*32+lane);
    v[18]=__ldg(e4+i4.z*32+lane); v[19]=__ldg(e4+i4.w*32+lane);

    float4 a;
    a.x = (((v[0].x+v[1].x)+(v[2].x+v[3].x))+((v[4].x+v[5].x)+(v[6].x+v[7].x)))
        + (((v[8].x+v[9].x)+(v[10].x+v[11].x))+((v[12].x+v[13].x)+(v[14].x+v[15].x)))
        + ((v[16].x+v[17].x)+(v[18].x+v[19].x));
    a.y = (((v[0].y+v[1].y)+(v[2].y+v[3].y))+((v[4].y+v[5].y)+(v[6].y+v[7].y)))
        + (((v[8].y+v[9].y)+(v[10].y+v[11].y))+((v[12].y+v[13].y)+(v[14].y+v[15].y)))
        + ((v[16].y+v[17].y)+(v[18].y+v[19].y));
    a.z = (((v[0].z+v[1].z)+(v[2].z+v[3].z))+((v[4].z+v[5].z)+(v[6].z+v[7].z)))
        + (((v[8].z+v[9].z)+(v[10].z+v[11].z))+((v[12].z+v[13].z)+(v[14].z+v[15].z)))
        + ((v[16].z+v[17].z)+(v[18].z+v[19].z));
    a.w = (((v[0].w+v[1].w)+(v[2].w+v[3].w))+((v[4].w+v[5].w)+(v[6].w+v[7].w)))
        + (((v[8].w+v[9].w)+(v[10].w+v[11].w))+((v[12].w+v[13].w)+(v[14].w+v[15].w)))
        + ((v[16].w+v[17].w)+(v[18].w+v[19].w));

    const float inv = 1.0f / (float)__ldg(bsz + r);
    a.x *= inv; a.y *= inv; a.z *= inv; a.w *= inv;
    ((float4*)g_ub)[r*32 + lane] = a;
}

__global__ void __launch_bounds__(256) k_gather(const int* __restrict__ ids,
                                                const int* __restrict__ bsz,
                                                const int* __restrict__ lens,
                                                const float* __restrict__ emb){
    const int p = blockIdx.x * 8 + (threadIdx.x >> 5);   // 0..6399
    const int lane = threadIdx.x & 31;
    const float4* e4 = (const float4*)emb;
    gather_row(p,         lane, ids, bsz, lens, e4);
    gather_row(12799 - p, lane, ids, bsz, lens, e4);
}

// ---------------------------------------------------------------------------
// K2: fused xg + scan. Singles+pairs scheduling:
//   bid <  NS : single row  b0 = bid              (len1 = 0)
//   bid >= NS : pair  b0 = bid, b1 = 255+NS-bid
// Phase B: flat job list, 16-slot ub ring, 8 dots per barrier.
// Phase C: gate threads preload their xg triple at step top (s_xg immutable),
//          dual conditional dots -> STS hg -> 256 one-element gates.
// SMEM: xg 2*50*384 + ub 16*128 + h 2*128 + hg 2*384 = 41472 fl = 165888 B
// ---------------------------------------------------------------------------
__global__ void __launch_bounds__(384,1) k_xgscan(
    const float* __restrict__ W_ih,
    const float* __restrict__ W_hh,
    const float* __restrict__ b_ih,
    const float* __restrict__ b_hh,
    const float* __restrict__ h0,
    const int*   __restrict__ lens,
    float*       __restrict__ out)
{
    extern __shared__ float smem[];
    float* s_xg = smem;                    // [2][TT][G3]
    float* s_ub = s_xg + 2*TT*G3;          // [16][EE] ring buffer
    float* s_h  = s_ub + 16*EE;            // [2][EE]
    float* s_hg = s_h + 2*EE;              // [2][G3]

    const int j   = threadIdx.x;
    const int bid = blockIdx.x;
    const bool dual = (bid >= NS);
    const int b0 = bid;
    const int b1 = dual ? (255 + NS - bid) : bid;
    const int len0 = __ldg(lens + b0);
    const int len1 = dual ? __ldg(lens + b1) : 0;
    const int total = len0 + len1;

    u64 w[64];

    // ---------------- Phase B: xg -> SMEM, flat job list, 8/barrier ------
    {
        const u64* wr = (const u64*)(W_ih + j*EE);
        #pragma unroll
        for (int k = 0; k < 64; ++k) w[k] = __ldg(wr + k);
    }
    const float bi = __ldg(b_ih + j);
    const int lane = j & 31, lw = j >> 5;

    if (lw < 8 && lw < total){                   // preload jobs 0..7
        const int rsel = (lw >= len0);
        const int t    = lw - (rsel ? len0 : 0);
        const int bb   = rsel ? b1 : b0;
        ((float4*)(s_ub + (lw & 15)*EE))[lane] =
            ((const float4*)(g_ub + (bb*TT + t)*EE))[lane];
    }
    __syncthreads();

    for (int i = 0; i < total; i += 8){
        float4 pf; bool hav = false;
        if (lw < 8){
            const int ii = i + 8 + lw;
            if (ii < total){
                const int rsel = (ii >= len0);
                const int t    = ii - (rsel ? len0 : 0);
                const int bb   = rsel ? b1 : b0;
                pf = ((const float4*)(g_ub + (bb*TT + t)*EE))[lane];
                hav = true;
            }
        }
        #pragma unroll
        for (int u = 0; u < 8; ++u){
            const int ii = i + u;
            if (ii < total){
                const int rsel = (ii >= len0);
                const int t    = ii - (rsel ? len0 : 0);
                s_xg[(rsel*TT + t)*G3 + j] = dot_s(w, s_ub + (ii & 15)*EE) + bi;
            }
        }
        if (hav)
            ((float4*)(s_ub + ((i + 8 + lw) & 15)*EE))[lane] = pf;
        __syncthreads();
    }

    // ---------------- Phase C: scan ----------------
    const int dep = zero_dep(s_xg[j]);           // keep W_hh load after phase B
    {
        const u64* wr = (const u64*)(W_hh + (j + dep)*EE);
        #pragma unroll
        for (int k = 0; k < 64; ++k) w[k] = __ldg(wr + k);
    }
    const float bh = __ldg(b_hh + j);

    if (j < EE){
        s_h[j]      = __ldg(h0 + b0*EE + j);
        s_h[EE + j] = dual ? __ldg(h0 + b1*EE + j) : 0.f;
    }
    __syncthreads();

    const int grow = j >> 7, ge = j & 127;       // gate role (j < 256)

    for (int t = 0; t < len0; ++t){
        const bool a1 = (t < len1);

        // gate-input prefetch: s_xg is immutable in phase C, so issue these
        // LDS at step top — they complete under the dot FMAs + barrier.
        float x0 = 0.f, x1 = 0.f, x2 = 0.f;
        if (j < 256){
            const float* xr = s_xg + (grow*TT + t)*G3;
            x0 = xr[ge]; x1 = xr[ge + 128]; x2 = xr[ge + 256];
        }

        const float hg0 = dot_s(w, s_h) + bh;
        float hg1 = 0.f;
        if (a1) hg1 = dot_s(w, s_h + EE) + bh;

        s_hg[j]      = hg0;
        s_hg[G3 + j] = hg1;
        __syncthreads();

        if (j < 256 && (grow == 0 || a1)){
            const float* hp = s_hg + grow*G3;
            const float r  = sigf(x0 + hp[ge]);
            const float z  = sigf(x1 + hp[ge + 128]);
            const float n  = tanh_hw(x2 + r * hp[ge + 256]);
            const float hv = z*(s_h[grow*EE + ge] - n) + n;
            s_h[grow*EE + ge] = hv;
            out[((grow ? b1 : b0)*TT + t)*EE + ge] = hv;
        }
        __syncthreads();
    }

    // ---------------- epilogue: masked tail zeros + h_u ----------------
    {
        const float4 z4 = make_float4(0.f, 0.f, 0.f, 0.f);
        float4* p0 = (float4*)(out + (b0*TT + len0)*EE);
        const int n0 = (TT - len0) * (EE/4);
        for (int k = j; k < n0; k += 384) p0[k] = z4;
        if (dual){
            float4* p1 = (float4*)(out + (b1*TT + len1)*EE);
            const int n1 = (TT - len1) * (EE/4);
            for (int k = j; k < n1; k += 384) p1[k] = z4;
        }
    }
    if (j < EE)
        out[BB*TT*EE + b0*EE + j] = s_h[j];
    else if (dual && j < 256)
        out[BB*TT*EE + b1*EE + (j - EE)] = s_h[j];
}

// ---------------------------------------------------------------------------
extern "C" void kernel_launch(void* const* d_in, const int* in_sizes, int n_in,
                              void* d_out, int out_size){
    const int*   item_ids = (const int*)  d_in[0];
    const int*   bsz      = (const int*)  d_in[1];
    const int*   lengths  = (const int*)  d_in[2];
    const float* emb      = (const float*)d_in[3];
    const float* W_ih     = (const float*)d_in[4];
    const float* W_hh     = (const float*)d_in[5];
    const float* b_ih     = (const float*)d_in[6];
    const float* b_hh     = (const float*)d_in[7];
    const float* h0       = (const float*)d_in[8];
    float* out = (float*)d_out;

    const int smem_bytes = (2*TT*G3 + 16*EE + 2*EE + 2*G3) * 4;   // 165888
    cudaFuncSetAttribute(k_xgscan, cudaFuncAttributeMaxDynamicSharedMemorySize,
                         smem_bytes);

    k_gather<<<800, 256>>>(item_ids, bsz, lengths, emb);
    k_xgscan<<<GRID, 384, smem_bytes>>>(W_ih, W_hh, b_ih, b_hh, h0,
                                        lengths, out);
}

// round 17
// speedup vs baseline: 1.0070x; 1.0070x over previous
#include <cuda_runtime.h>

#define BB 256
#define TT 50
#define MM 20
#define EE 128
#define G3 384
#define NS 40            // single-row CTAs (longest rows)
#define GRID 148         // NS + (256-NS)/2

typedef unsigned long long u64;

// scratch (no cudaMalloc allowed)
__device__ __align__(16) float g_ub[BB*TT*EE];   // basket means (B,T,E)

__device__ __forceinline__ void fma2(u64 &acc, u64 a, u64 b){
    asm("fma.rn.f32x2 %0, %1, %2, %0;" : "+l"(acc) : "l"(a), "l"(b));
}
__device__ __forceinline__ u64 add2(u64 a, u64 b){
    u64 r; asm("add.rn.f32x2 %0, %1, %2;" : "=l"(r) : "l"(a), "l"(b));
    return r;
}
__device__ __forceinline__ float hsum2(u64 v){
    float lo, hi;
    asm("mov.b64 {%0,%1}, %2;" : "=f"(lo), "=f"(hi) : "l"(v));
    return lo + hi;
}
__device__ __forceinline__ float tanh_hw(float x){
    float y; asm("tanh.approx.f32 %0, %1;" : "=f"(y) : "f"(x));
    return y;
}
__device__ __forceinline__ float sigf(float x){          // 1 MUFU
    return 0.5f + 0.5f * tanh_hw(0.5f * x);
}
__device__ __forceinline__ int zero_dep(float x){
    int r;
    asm("{\n\t.reg .b32 t;\n\tmov.b32 t, %1;\n\tand.b32 %0, t, 0;\n\t}"
        : "=r"(r) : "f"(x));
    return r;
}

// dot of this thread's W row with a 128-float vector in SMEM (broadcast LDS)
__device__ __forceinline__ float dot_s(const u64* __restrict__ w,
                                       const float* __restrict__ src){
    u64 ca = 0ull, cb = 0ull;
    const ulonglong2* hp = (const ulonglong2*)src;
    #pragma unroll
    for (int k = 0; k < 32; ++k){
        ulonglong2 v = hp[k];
        fma2(ca, w[2*k  ], v.x);
        fma2(cb, w[2*k+1], v.y);
    }
    return hsum2(add2(ca, cb));
}

// ---------------------------------------------------------------------------
// K1: gather — low-register version (DRAM-latency bound; ~4us steady-state
// with emb L2-resident). One WARP per PAIR of rows (p, 12799-p).
// ---------------------------------------------------------------------------
__device__ __forceinline__ void gather_row(int r, int lane,
                                           const int* __restrict__ ids,
                                           const int* __restrict__ bsz,
                                           const int* __restrict__ lens,
                                           const float4* __restrict__ e4){
    const int b = r / TT;
    const int t = r - b*TT;
    if (t >= __ldg(lens + b)) return;             // uniform per warp

    const int4* ip = (const int4*)(ids + r*MM);   // 20 ids = 5 int4, broadcast
    const int4 i0 = __ldg(ip+0), i1 = __ldg(ip+1), i2 = __ldg(ip+2),
               i3 = __ldg(ip+3), i4 = __ldg(ip+4);

    float4 v[20];
    v[0]=__ldg(e4+i0.x*32+lane);  v[1]=__ldg(e4+i0.y*32+lane);
    v[2]=__ldg(e4+i0.z*32+lane);  v[3]=__ldg(e4+i0.w*32+lane);
    v[4]=__ldg(e4+i1.x*32+lane);  v[5]=__ldg(e4+i1.y*32+lane);
    v[6]=__ldg(e4+i1.z*32+lane);  v[7]=__ldg(e4+i1.w*32+lane);
    v[8]=__ldg(e4+i2.x*32+lane);  v[9]=__ldg(e4+i2.y*32+lane);
    v[10]=__ldg(e4+i2.z*32+lane); v[11]=__ldg(e4+i2.w*32+lane);
    v[12]=__ldg(e4+i3.x*32+lane); v[13]=__ldg(e4+i3.y*32+lane);
    v[14]=__ldg(e4+i3.z*32+lane); v[15]=__ldg(e4+i3.w*32+lane);
    v[16]=__ldg(e4+i4.x*32+lane); v[17]=__ldg(e4+i4.y*32+lane);
    v[18]=__ldg(e4+i4.z*32+lane); v[19]=__ldg(e4+i4.w*32+lane);

    float4 a;
    a.x = (((v[0].x+v[1].x)+(v[2].x+v[3].x))+((v[4].x+v[5].x)+(v[6].x+v[7].x)))
        + (((v[8].x+v[9].x)+(v[10].x+v[11].x))+((v[12].x+v[13].x)+(v[14].x+v[15].x)))
        + ((v[16].x+v[17].x)+(v[18].x+v[19].x));
    a.y = (((v[0].y+v[1].y)+(v[2].y+v[3].y))+((v[4].y+v[5].y)+(v[6].y+v[7].y)))
        + (((v[8].y+v[9].y)+(v[10].y+v[11].y))+((v[12].y+v[13].y)+(v[14].y+v[15].y)))
        + ((v[16].y+v[17].y)+(v[18].y+v[19].y));
    a.z = (((v[0].z+v[1].z)+(v[2].z+v[3].z))+((v[4].z+v[5].z)+(v[6].z+v[7].z)))
        + (((v[8].z+v[9].z)+(v[10].z+v[11].z))+((v[12].z+v[13].z)+(v[14].z+v[15].z)))
        + ((v[16].z+v[17].z)+(v[18].z+v[19].z));
    a.w = (((v[0].w+v[1].w)+(v[2].w+v[3].w))+((v[4].w+v[5].w)+(v[6].w+v[7].w)))
        + (((v[8].w+v[9].w)+(v[10].w+v[11].w))+((v[12].w+v[13].w)+(v[14].w+v[15].w)))
        + ((v[16].w+v[17].w)+(v[18].w+v[19].w));

    const float inv = 1.0f / (float)__ldg(bsz + r);
    a.x *= inv; a.y *= inv; a.z *= inv; a.w *= inv;
    ((float4*)g_ub)[r*32 + lane] = a;
}

__global__ void __launch_bounds__(256) k_gather(const int* __restrict__ ids,
                                                const int* __restrict__ bsz,
                                                const int* __restrict__ lens,
                                                const float* __restrict__ emb){
    const int p = blockIdx.x * 8 + (threadIdx.x >> 5);   // 0..6399
    const int lane = threadIdx.x & 31;
    const float4* e4 = (const float4*)emb;
    gather_row(p,         lane, ids, bsz, lens, e4);
    gather_row(12799 - p, lane, ids, bsz, lens, e4);
}

// ---------------------------------------------------------------------------
// K2: fused xg + scan — R15 champion structure restored.
//   bid <  NS : single row  b0 = bid              (len1 = 0)
//   bid >= NS : pair  b0 = bid, b1 = 255+NS-bid
// Phase B: flat job list, 8-slot ub ring, 4 dots per barrier (R15).
// Phase C: dual conditional dots -> STS hg (hg1 guarded) -> 256 one-element
//          gates (xg/hg read post-barrier; h_prev prefetched at step top).
// SMEM: xg 2*50*384 + ub 8*128 + h 2*128 + hg 2*384 = 40448 fl = 161792 B
// ---------------------------------------------------------------------------
__global__ void __launch_bounds__(384,1) k_xgscan(
    const float* __restrict__ W_ih,
    const float* __restrict__ W_hh,
    const float* __restrict__ b_ih,
    const float* __restrict__ b_hh,
    const float* __restrict__ h0,
    const int*   __restrict__ lens,
    float*       __restrict__ out)
{
    extern __shared__ float smem[];
    float* s_xg = smem;                    // [2][TT][G3]
    float* s_ub = s_xg + 2*TT*G3;          // [8][EE] ring buffer
    float* s_h  = s_ub + 8*EE;             // [2][EE]
    float* s_hg = s_h + 2*EE;              // [2][G3]

    const int j   = threadIdx.x;
    const int bid = blockIdx.x;
    const bool dual = (bid >= NS);
    const int b0 = bid;
    const int b1 = dual ? (255 + NS - bid) : bid;
    const int len0 = __ldg(lens + b0);
    const int len1 = dual ? __ldg(lens + b1) : 0;
    const int total = len0 + len1;

    u64 w[64];

    // ---------------- Phase B: xg -> SMEM, flat job list, 4/barrier ------
    {
        const u64* wr = (const u64*)(W_ih + j*EE);
        #pragma unroll
        for (int k = 0; k < 64; ++k) w[k] = __ldg(wr + k);
    }
    const float bi = __ldg(b_ih + j);
    const int lane = j & 31, lw = j >> 5;

    if (lw < 4 && lw < total){                   // preload jobs 0..3
        const int rsel = (lw >= len0);
        const int t    = lw - (rsel ? len0 : 0);
        const int bb   = rsel ? b1 : b0;
        ((float4*)(s_ub + (lw & 7)*EE))[lane] =
            ((const float4*)(g_ub + (bb*TT + t)*EE))[lane];
    }
    __syncthreads();

    for (int i = 0; i < total; i += 4){
        float4 pf; bool hav = false;
        if (lw < 4){
            const int ii = i + 4 + lw;
            if (ii < total){
                const int rsel = (ii >= len0);
                const int t    = ii - (rsel ? len0 : 0);
                const int bb   = rsel ? b1 : b0;
                pf = ((const float4*)(g_ub + (bb*TT + t)*EE))[lane];
                hav = true;
            }
        }
        #pragma unroll
        for (int u = 0; u < 4; ++u){
            const int ii = i + u;
            if (ii < total){
                const int rsel = (ii >= len0);
                const int t    = ii - (rsel ? len0 : 0);
                s_xg[(rsel*TT + t)*G3 + j] = dot_s(w, s_ub + (ii & 7)*EE) + bi;
            }
        }
        if (hav)
            ((float4*)(s_ub + ((i + 4 + lw) & 7)*EE))[lane] = pf;
        __syncthreads();
    }

    // ---------------- Phase C: scan ----------------
    const int dep = zero_dep(s_xg[j]);           // keep W_hh load after phase B
    {
        const u64* wr = (const u64*)(W_hh + (j + dep)*EE);
        #pragma unroll
        for (int k = 0; k < 64; ++k) w[k] = __ldg(wr + k);
    }
    const float bh = __ldg(b_hh + j);

    if (j < EE){
        s_h[j]      = __ldg(h0 + b0*EE + j);
        s_h[EE + j] = dual ? __ldg(h0 + b1*EE + j) : 0.f;
    }
    __syncthreads();

    const int grow = j >> 7, ge = j & 127;       // gate role (j < 256)

    for (int t = 0; t < len0; ++t){
        const bool a1 = (t < len1);

        // h_prev prefetch: s_h is stable from prev step's closing barrier
        // until this step's gate writes — pull it off the gate critical path.
        float hprev = 0.f;
        if (j < 256) hprev = s_h[grow*EE + ge];

        const float hg0 = dot_s(w, s_h) + bh;
        float hg1 = 0.f;
        if (a1) hg1 = dot_s(w, s_h + EE) + bh;

        s_hg[j] = hg0;
        if (a1) s_hg[G3 + j] = hg1;              // stale slot never read
        __syncthreads();

        if (j < 256 && (grow == 0 || a1)){
            const float* xr = s_xg + (grow*TT + t)*G3;
            const float* hp = s_hg + grow*G3;
            const float r  = sigf(xr[ge]       + hp[ge]);
            const float z  = sigf(xr[ge + 128] + hp[ge + 128]);
            const float n  = tanh_hw(xr[ge + 256] + r * hp[ge + 256]);
            const float hv = z*(hprev - n) + n;
            s_h[grow*EE + ge] = hv;
            out[((grow ? b1 : b0)*TT + t)*EE + ge] = hv;
        }
        __syncthreads();
    }

    // ---------------- epilogue: masked tail zeros + h_u ----------------
    {
        const float4 z4 = make_float4(0.f, 0.f, 0.f, 0.f);
        float4* p0 = (float4*)(out + (b0*TT + len0)*EE);
        const int n0 = (TT - len0) * (EE/4);
        for (int k = j; k < n0; k += 384) p0[k] = z4;
        if (dual){
            float4* p1 = (float4*)(out + (b1*TT + len1)*EE);
            const int n1 = (TT - len1) * (EE/4);
            for (int k = j; k < n1; k += 384) p1[k] = z4;
        }
    }
    if (j < EE)
        out[BB*TT*EE + b0*EE + j] = s_h[j];
    else if (dual && j < 256)
        out[BB*TT*EE + b1*EE + (j - EE)] = s_h[j];
}

// ---------------------------------------------------------------------------
extern "C" void kernel_launch(void* const* d_in, const int* in_sizes, int n_in,
                              void* d_out, int out_size){
    const int*   item_ids = (const int*)  d_in[0];
    const int*   bsz      = (const int*)  d_in[1];
    const int*   lengths  = (const int*)  d_in[2];
    const float* emb      = (const float*)d_in[3];
    const float* W_ih     = (const float*)d_in[4];
    const float* W_hh     = (const float*)d_in[5];
    const float* b_ih     = (const float*)d_in[6];
    const float* b_hh     = (const float*)d_in[7];
    const float* h0       = (const float*)d_in[8];
    float* out = (float*)d_out;

    const int smem_bytes = (2*TT*G3 + 8*EE + 2*EE + 2*G3) * 4;   // 161792
    cudaFuncSetAttribute(k_xgscan, cudaFuncAttributeMaxDynamicSharedMemorySize,
                         smem_bytes);

    k_gather<<<800, 256>>>(item_ids, bsz, lengths, emb);
    k_xgscan<<<GRID, 384, smem_bytes>>>(W_ih, W_hh, b_ih, b_hh, h0,
                                        lengths, out);
}